// round 4
// baseline (speedup 1.0000x reference)
#include <cuda_runtime.h>

// Cumulative matrix product (associative scan of matmul) over axis 1.
// input:  (32, 256, 128, 128) fp32
// output: x (32,128,128) followed by all_outputs (32,256,128,128), flat.
//
// Chunked scan; matmul core = 3xTF32 tensor MMA (m16n8k8) with the hi/lo
// split hoisted to tile-load time: smem holds interleaved (hi,lo) float2
// pairs so the inner loop is pure LDS.64 + HMMA. Global loads for the next
// k-slab are prefetched into registers during the current slab's MMAs.

#define DN 128
#define BATCH 32
#define SEQ 256
#define CH 16   // number of chunks
#define CL 16   // chunk length
#define KS 16   // K slab

// scratch for chunk-total scan (ping-pong)
__device__ float g_scr0[(size_t)BATCH * CH * DN * DN];
__device__ float g_scr1[(size_t)BATCH * CH * DN * DN];

__device__ __forceinline__ void copy128(const float* __restrict__ s, float* __restrict__ d) {
    const float4* s4 = (const float4*)s;
    float4* d4 = (float4*)d;
#pragma unroll
    for (int i = threadIdx.x; i < DN * DN / 4; i += 256) d4[i] = s4[i];
}

__device__ __forceinline__ unsigned f2tf32(float x) {
    unsigned r;
    asm("cvt.rna.tf32.f32 %0, %1;" : "=r"(r) : "f"(x));
    return r;
}

// one-time split: (hi, lo) both valid tf32 bit patterns stored in float slots
__device__ __forceinline__ float2 split_tf32(float x) {
    unsigned h = f2tf32(x);
    float lo = x - __uint_as_float(h);
    unsigned l = f2tf32(lo);
    return make_float2(__uint_as_float(h), __uint_as_float(l));
}

__device__ __forceinline__ void mma8(float c[4], const unsigned a[4], const unsigned b[2]) {
    asm volatile(
        "mma.sync.aligned.m16n8k8.row.col.f32.tf32.tf32.f32 "
        "{%0,%1,%2,%3},{%4,%5,%6,%7},{%8,%9},{%0,%1,%2,%3};"
        : "+f"(c[0]), "+f"(c[1]), "+f"(c[2]), "+f"(c[3])
        : "r"(a[0]), "r"(a[1]), "r"(a[2]), "r"(a[3]), "r"(b[0]), "r"(b[1]));
}

// Block of 256 threads (8 warps): C = A(128x128) @ B(128x128), row-major fp32,
// 3xTF32 (hi*hi + lo*hi + hi*lo). Cout may alias B (all global B reads retire
// to registers before the last slab's pre-MMA sync; C stores come after all
// MMAs). The entry __syncthreads makes chained calls (Cout of call j-1 used
// as A of call j by the same block) safe.
#define ASTR 20    // As row stride in float2 (160B: q*32+kq*8 banks distinct)
#define BSTR 132   // Bs row stride in float2 (1056B: kq*32+q*8 banks distinct)
__device__ __forceinline__ void mm128(const float* __restrict__ A,
                                      const float* __restrict__ B,
                                      float* __restrict__ Cout) {
    __shared__ float2 As[DN][ASTR];   // [m][k] (hi,lo)
    __shared__ float2 Bs[KS][BSTR];   // [k][n] (hi,lo)

    const int tid = threadIdx.x;
    const int lane = tid & 31;
    const int w = tid >> 5;
    const int wm = (w >> 2) * 64;   // warp m origin (0 or 64)
    const int wn = (w & 3) * 32;    // warp n origin
    const int q = lane >> 2;        // 0..7
    const int kq = lane & 3;        // 0..3

    // load/split thread mapping
    const int am = tid >> 2;            // 0..63
    const int ac = (tid & 3) * 4;       // 0,4,8,12
    const int br = tid >> 5;            // 0..7
    const int bc = (tid & 31) * 4;      // 0..124

    float acc[4][4][4];
#pragma unroll
    for (int mt = 0; mt < 4; mt++)
#pragma unroll
        for (int nt = 0; nt < 4; nt++)
#pragma unroll
            for (int i = 0; i < 4; i++) acc[mt][nt][i] = 0.0f;

    __syncthreads();  // orders prior-call C stores before our A/B loads

    float4 ra0, ra1, rb0, rb1;
    // prefetch slab 0
    ra0 = *(const float4*)&A[(size_t)am * DN + ac];
    ra1 = *(const float4*)&A[(size_t)(am + 64) * DN + ac];
    rb0 = *(const float4*)&B[(size_t)br * DN + bc];
    rb1 = *(const float4*)&B[(size_t)(br + 8) * DN + bc];

    for (int k0 = 0; k0 < DN; k0 += KS) {
        __syncthreads();  // previous slab fully consumed by MMAs
        // split + store current slab
        As[am][ac + 0] = split_tf32(ra0.x);
        As[am][ac + 1] = split_tf32(ra0.y);
        As[am][ac + 2] = split_tf32(ra0.z);
        As[am][ac + 3] = split_tf32(ra0.w);
        As[am + 64][ac + 0] = split_tf32(ra1.x);
        As[am + 64][ac + 1] = split_tf32(ra1.y);
        As[am + 64][ac + 2] = split_tf32(ra1.z);
        As[am + 64][ac + 3] = split_tf32(ra1.w);
        Bs[br][bc + 0] = split_tf32(rb0.x);
        Bs[br][bc + 1] = split_tf32(rb0.y);
        Bs[br][bc + 2] = split_tf32(rb0.z);
        Bs[br][bc + 3] = split_tf32(rb0.w);
        Bs[br + 8][bc + 0] = split_tf32(rb1.x);
        Bs[br + 8][bc + 1] = split_tf32(rb1.y);
        Bs[br + 8][bc + 2] = split_tf32(rb1.z);
        Bs[br + 8][bc + 3] = split_tf32(rb1.w);
        __syncthreads();

        // prefetch next slab while MMAs run
        if (k0 + KS < DN) {
            const int kn = k0 + KS;
            ra0 = *(const float4*)&A[(size_t)am * DN + kn + ac];
            ra1 = *(const float4*)&A[(size_t)(am + 64) * DN + kn + ac];
            rb0 = *(const float4*)&B[(size_t)(kn + br) * DN + bc];
            rb1 = *(const float4*)&B[(size_t)(kn + br + 8) * DN + bc];
        }

#pragma unroll
        for (int kk = 0; kk < KS; kk += 8) {
            float2 bf[4][2];
#pragma unroll
            for (int nt = 0; nt < 4; nt++) {
                bf[nt][0] = Bs[kk + kq][wn + nt * 8 + q];
                bf[nt][1] = Bs[kk + kq + 4][wn + nt * 8 + q];
            }
#pragma unroll
            for (int mt = 0; mt < 4; mt++) {
                float2 a0 = As[wm + mt * 16 + q][kk + kq];
                float2 a1 = As[wm + mt * 16 + q + 8][kk + kq];
                float2 a2 = As[wm + mt * 16 + q][kk + kq + 4];
                float2 a3 = As[wm + mt * 16 + q + 8][kk + kq + 4];
                unsigned ah[4] = {__float_as_uint(a0.x), __float_as_uint(a1.x),
                                  __float_as_uint(a2.x), __float_as_uint(a3.x)};
                unsigned al[4] = {__float_as_uint(a0.y), __float_as_uint(a1.y),
                                  __float_as_uint(a2.y), __float_as_uint(a3.y)};
#pragma unroll
                for (int nt = 0; nt < 4; nt++) {
                    unsigned bh[2] = {__float_as_uint(bf[nt][0].x), __float_as_uint(bf[nt][1].x)};
                    unsigned bl[2] = {__float_as_uint(bf[nt][0].y), __float_as_uint(bf[nt][1].y)};
                    mma8(acc[mt][nt], ah, bh);
                    mma8(acc[mt][nt], al, bh);
                    mma8(acc[mt][nt], ah, bl);
                }
            }
        }
    }

    // Store C (all global B reads retired block-wide before this point)
#pragma unroll
    for (int mt = 0; mt < 4; mt++)
#pragma unroll
        for (int nt = 0; nt < 4; nt++) {
            int r0 = wm + mt * 16 + q;
            int c0 = wn + nt * 8 + 2 * kq;
            *(float2*)&Cout[(size_t)r0 * DN + c0] = make_float2(acc[mt][nt][0], acc[mt][nt][1]);
            *(float2*)&Cout[(size_t)(r0 + 8) * DN + c0] = make_float2(acc[mt][nt][2], acc[mt][nt][3]);
        }
}

// Pass 1: local prefix products within each chunk (written into all_outputs).
__global__ void __launch_bounds__(256, 2) k_pass1(const float* __restrict__ in,
                                                  float* __restrict__ outAll) {
    const int b = blockIdx.x / CH;
    const int c = blockIdx.x % CH;
    const size_t base = ((size_t)b * SEQ + (size_t)c * CL) * (DN * DN);
    const float* E = in + base;
    float* O = outAll + base;
    copy128(E, O);
    for (int j = 1; j < CL; j++) {
        mm128(O + (size_t)(j - 1) * DN * DN,
              E + (size_t)j * DN * DN,
              O + (size_t)j * DN * DN);
    }
}

// Pass 2 step (Hillis-Steele over chunk totals): dst[b,i] = src[b,i-d] @ src[b,i]
__global__ void __launch_bounds__(256, 2) k_scan(const float* __restrict__ src,
                                                 size_t soff, size_t sb, size_t si,
                                                 float* __restrict__ dst, int d) {
    const int b = blockIdx.x / CH;
    const int i = blockIdx.x % CH;
    const float* Ti = src + soff + (size_t)b * sb + (size_t)i * si;
    float* Dp = dst + ((size_t)b * CH + i) * (DN * DN);
    if (i < d) {
        copy128(Ti, Dp);
        return;
    }
    const float* Ta = src + soff + (size_t)b * sb + (size_t)(i - d) * si;
    mm128(Ta, Ti, Dp);
}

// Pass 3: apply exclusive chunk prefix to chunks 1..CH-1 (in place).
__global__ void __launch_bounds__(256, 2) k_pass3(float* __restrict__ outAll,
                                                  const float* __restrict__ scan) {
    int idx = blockIdx.x;
    const int j = idx % CL; idx /= CL;
    const int c = (idx % (CH - 1)) + 1; idx /= (CH - 1);
    const int b = idx;
    const float* A = scan + ((size_t)b * CH + (c - 1)) * (DN * DN);
    float* Bp = outAll + ((size_t)b * SEQ + (size_t)c * CL + j) * (DN * DN);
    mm128(A, Bp, Bp);
}

// Pass 4: x[b] = all_outputs[b, SEQ-1]
__global__ void __launch_bounds__(256) k_copy_x(const float* __restrict__ outAll,
                                                float* __restrict__ x) {
    const int b = blockIdx.x;
    copy128(outAll + ((size_t)b * SEQ + (SEQ - 1)) * (DN * DN),
            x + (size_t)b * DN * DN);
}

extern "C" void kernel_launch(void* const* d_in, const int* in_sizes, int n_in,
                              void* d_out, int out_size) {
    const float* in = (const float*)d_in[0];
    float* out = (float*)d_out;
    float* x = out;                                  // first 32*128*128 elements
    float* outAll = out + (size_t)BATCH * DN * DN;   // then 32*256*128*128

    float *scr0, *scr1;
    cudaGetSymbolAddress((void**)&scr0, g_scr0);
    cudaGetSymbolAddress((void**)&scr1, g_scr1);

    const size_t MM = (size_t)DN * DN;

    k_pass1<<<BATCH * CH, 256>>>(in, outAll);
    // Hillis-Steele over chunk totals: totals live at element (c+1)*CL-1 of outAll
    k_scan<<<BATCH * CH, 256>>>(outAll, (size_t)(CL - 1) * MM,
                                (size_t)SEQ * MM, (size_t)CL * MM, scr0, 1);
    k_scan<<<BATCH * CH, 256>>>(scr0, 0, (size_t)CH * MM, MM, scr1, 2);
    k_scan<<<BATCH * CH, 256>>>(scr1, 0, (size_t)CH * MM, MM, scr0, 4);
    k_scan<<<BATCH * CH, 256>>>(scr0, 0, (size_t)CH * MM, MM, scr1, 8);
    k_pass3<<<BATCH * (CH - 1) * CL, 256>>>(outAll, scr1);
    k_copy_x<<<BATCH, 256>>>(outAll, x);
}

// round 5
// speedup vs baseline: 1.0023x; 1.0023x over previous
#include <cuda_runtime.h>

// Cumulative matrix product (associative scan of matmul) over axis 1.
// input:  (32, 256, 128, 128) fp32
// output: x (32,128,128) followed by all_outputs (32,256,128,128), flat.
//
// Chunked scan; matmul core = 3xTF32 tensor MMA (m16n8k8) with the hi/lo
// split hoisted to tile-load time: smem holds interleaved (hi,lo) float2
// pairs so the inner loop is pure LDS.64 + HMMA. Global loads for the next
// k-slab are prefetched into registers during the current slab's MMAs.

#define DN 128
#define BATCH 32
#define SEQ 256
#define CH 16   // number of chunks
#define CL 16   // chunk length
#define KS 16   // K slab

// scratch for chunk-total scan (ping-pong)
__device__ float g_scr0[(size_t)BATCH * CH * DN * DN];
__device__ float g_scr1[(size_t)BATCH * CH * DN * DN];

__device__ __forceinline__ void copy128(const float* __restrict__ s, float* __restrict__ d) {
    const float4* s4 = (const float4*)s;
    float4* d4 = (float4*)d;
#pragma unroll
    for (int i = threadIdx.x; i < DN * DN / 4; i += 256) d4[i] = s4[i];
}

__device__ __forceinline__ unsigned f2tf32(float x) {
    unsigned r;
    asm("cvt.rna.tf32.f32 %0, %1;" : "=r"(r) : "f"(x));
    return r;
}

// one-time split: (hi, lo) both valid tf32 bit patterns stored in float slots
__device__ __forceinline__ float2 split_tf32(float x) {
    unsigned h = f2tf32(x);
    float lo = x - __uint_as_float(h);
    unsigned l = f2tf32(lo);
    return make_float2(__uint_as_float(h), __uint_as_float(l));
}

__device__ __forceinline__ void mma8(float c[4], const unsigned a[4], const unsigned b[2]) {
    asm volatile(
        "mma.sync.aligned.m16n8k8.row.col.f32.tf32.tf32.f32 "
        "{%0,%1,%2,%3},{%4,%5,%6,%7},{%8,%9},{%0,%1,%2,%3};"
        : "+f"(c[0]), "+f"(c[1]), "+f"(c[2]), "+f"(c[3])
        : "r"(a[0]), "r"(a[1]), "r"(a[2]), "r"(a[3]), "r"(b[0]), "r"(b[1]));
}

// Block of 256 threads (8 warps): C = A(128x128) @ B(128x128), row-major fp32,
// 3xTF32 (hi*hi + lo*hi + hi*lo). Cout may alias B (all global B reads retire
// to registers before the last slab's pre-MMA sync; C stores come after all
// MMAs). The entry __syncthreads makes chained calls (Cout of call j-1 used
// as A of call j by the same block) safe.
#define ASTR 20    // As row stride in float2 (160B: q*32+kq*8 banks distinct)
#define BSTR 132   // Bs row stride in float2 (1056B: kq*32+q*8 banks distinct)
__device__ __forceinline__ void mm128(const float* __restrict__ A,
                                      const float* __restrict__ B,
                                      float* __restrict__ Cout) {
    __shared__ float2 As[DN][ASTR];   // [m][k] (hi,lo)
    __shared__ float2 Bs[KS][BSTR];   // [k][n] (hi,lo)

    const int tid = threadIdx.x;
    const int lane = tid & 31;
    const int w = tid >> 5;
    const int wm = (w >> 2) * 64;   // warp m origin (0 or 64)
    const int wn = (w & 3) * 32;    // warp n origin
    const int q = lane >> 2;        // 0..7
    const int kq = lane & 3;        // 0..3

    // load/split thread mapping
    const int am = tid >> 2;            // 0..63
    const int ac = (tid & 3) * 4;       // 0,4,8,12
    const int br = tid >> 5;            // 0..7
    const int bc = (tid & 31) * 4;      // 0..124

    float acc[4][4][4];
#pragma unroll
    for (int mt = 0; mt < 4; mt++)
#pragma unroll
        for (int nt = 0; nt < 4; nt++)
#pragma unroll
            for (int i = 0; i < 4; i++) acc[mt][nt][i] = 0.0f;

    __syncthreads();  // orders prior-call C stores before our A/B loads

    float4 ra0, ra1, rb0, rb1;
    // prefetch slab 0
    ra0 = *(const float4*)&A[(size_t)am * DN + ac];
    ra1 = *(const float4*)&A[(size_t)(am + 64) * DN + ac];
    rb0 = *(const float4*)&B[(size_t)br * DN + bc];
    rb1 = *(const float4*)&B[(size_t)(br + 8) * DN + bc];

    for (int k0 = 0; k0 < DN; k0 += KS) {
        __syncthreads();  // previous slab fully consumed by MMAs
        // split + store current slab
        As[am][ac + 0] = split_tf32(ra0.x);
        As[am][ac + 1] = split_tf32(ra0.y);
        As[am][ac + 2] = split_tf32(ra0.z);
        As[am][ac + 3] = split_tf32(ra0.w);
        As[am + 64][ac + 0] = split_tf32(ra1.x);
        As[am + 64][ac + 1] = split_tf32(ra1.y);
        As[am + 64][ac + 2] = split_tf32(ra1.z);
        As[am + 64][ac + 3] = split_tf32(ra1.w);
        Bs[br][bc + 0] = split_tf32(rb0.x);
        Bs[br][bc + 1] = split_tf32(rb0.y);
        Bs[br][bc + 2] = split_tf32(rb0.z);
        Bs[br][bc + 3] = split_tf32(rb0.w);
        Bs[br + 8][bc + 0] = split_tf32(rb1.x);
        Bs[br + 8][bc + 1] = split_tf32(rb1.y);
        Bs[br + 8][bc + 2] = split_tf32(rb1.z);
        Bs[br + 8][bc + 3] = split_tf32(rb1.w);
        __syncthreads();

        // prefetch next slab while MMAs run
        if (k0 + KS < DN) {
            const int kn = k0 + KS;
            ra0 = *(const float4*)&A[(size_t)am * DN + kn + ac];
            ra1 = *(const float4*)&A[(size_t)(am + 64) * DN + kn + ac];
            rb0 = *(const float4*)&B[(size_t)(kn + br) * DN + bc];
            rb1 = *(const float4*)&B[(size_t)(kn + br + 8) * DN + bc];
        }

#pragma unroll
        for (int kk = 0; kk < KS; kk += 8) {
            float2 bf[4][2];
#pragma unroll
            for (int nt = 0; nt < 4; nt++) {
                bf[nt][0] = Bs[kk + kq][wn + nt * 8 + q];
                bf[nt][1] = Bs[kk + kq + 4][wn + nt * 8 + q];
            }
#pragma unroll
            for (int mt = 0; mt < 4; mt++) {
                float2 a0 = As[wm + mt * 16 + q][kk + kq];
                float2 a1 = As[wm + mt * 16 + q + 8][kk + kq];
                float2 a2 = As[wm + mt * 16 + q][kk + kq + 4];
                float2 a3 = As[wm + mt * 16 + q + 8][kk + kq + 4];
                unsigned ah[4] = {__float_as_uint(a0.x), __float_as_uint(a1.x),
                                  __float_as_uint(a2.x), __float_as_uint(a3.x)};
                unsigned al[4] = {__float_as_uint(a0.y), __float_as_uint(a1.y),
                                  __float_as_uint(a2.y), __float_as_uint(a3.y)};
#pragma unroll
                for (int nt = 0; nt < 4; nt++) {
                    unsigned bh[2] = {__float_as_uint(bf[nt][0].x), __float_as_uint(bf[nt][1].x)};
                    unsigned bl[2] = {__float_as_uint(bf[nt][0].y), __float_as_uint(bf[nt][1].y)};
                    mma8(acc[mt][nt], ah, bh);
                    mma8(acc[mt][nt], al, bh);
                    mma8(acc[mt][nt], ah, bl);
                }
            }
        }
    }

    // Store C (all global B reads retired block-wide before this point)
#pragma unroll
    for (int mt = 0; mt < 4; mt++)
#pragma unroll
        for (int nt = 0; nt < 4; nt++) {
            int r0 = wm + mt * 16 + q;
            int c0 = wn + nt * 8 + 2 * kq;
            *(float2*)&Cout[(size_t)r0 * DN + c0] = make_float2(acc[mt][nt][0], acc[mt][nt][1]);
            *(float2*)&Cout[(size_t)(r0 + 8) * DN + c0] = make_float2(acc[mt][nt][2], acc[mt][nt][3]);
        }
}

// Pass 1: local prefix products within each chunk (written into all_outputs).
__global__ void __launch_bounds__(256, 2) k_pass1(const float* __restrict__ in,
                                                  float* __restrict__ outAll) {
    const int b = blockIdx.x / CH;
    const int c = blockIdx.x % CH;
    const size_t base = ((size_t)b * SEQ + (size_t)c * CL) * (DN * DN);
    const float* E = in + base;
    float* O = outAll + base;
    copy128(E, O);
    for (int j = 1; j < CL; j++) {
        mm128(O + (size_t)(j - 1) * DN * DN,
              E + (size_t)j * DN * DN,
              O + (size_t)j * DN * DN);
    }
}

// Pass 2 step (Hillis-Steele over chunk totals): dst[b,i] = src[b,i-d] @ src[b,i]
__global__ void __launch_bounds__(256, 2) k_scan(const float* __restrict__ src,
                                                 size_t soff, size_t sb, size_t si,
                                                 float* __restrict__ dst, int d) {
    const int b = blockIdx.x / CH;
    const int i = blockIdx.x % CH;
    const float* Ti = src + soff + (size_t)b * sb + (size_t)i * si;
    float* Dp = dst + ((size_t)b * CH + i) * (DN * DN);
    if (i < d) {
        copy128(Ti, Dp);
        return;
    }
    const float* Ta = src + soff + (size_t)b * sb + (size_t)(i - d) * si;
    mm128(Ta, Ti, Dp);
}

// Pass 3: apply exclusive chunk prefix to chunks 1..CH-1 (in place).
__global__ void __launch_bounds__(256, 2) k_pass3(float* __restrict__ outAll,
                                                  const float* __restrict__ scan) {
    int idx = blockIdx.x;
    const int j = idx % CL; idx /= CL;
    const int c = (idx % (CH - 1)) + 1; idx /= (CH - 1);
    const int b = idx;
    const float* A = scan + ((size_t)b * CH + (c - 1)) * (DN * DN);
    float* Bp = outAll + ((size_t)b * SEQ + (size_t)c * CL + j) * (DN * DN);
    mm128(A, Bp, Bp);
}

// Pass 4: x[b] = all_outputs[b, SEQ-1]
__global__ void __launch_bounds__(256) k_copy_x(const float* __restrict__ outAll,
                                                float* __restrict__ x) {
    const int b = blockIdx.x;
    copy128(outAll + ((size_t)b * SEQ + (SEQ - 1)) * (DN * DN),
            x + (size_t)b * DN * DN);
}

extern "C" void kernel_launch(void* const* d_in, const int* in_sizes, int n_in,
                              void* d_out, int out_size) {
    const float* in = (const float*)d_in[0];
    float* out = (float*)d_out;
    float* x = out;                                  // first 32*128*128 elements
    float* outAll = out + (size_t)BATCH * DN * DN;   // then 32*256*128*128

    float *scr0, *scr1;
    cudaGetSymbolAddress((void**)&scr0, g_scr0);
    cudaGetSymbolAddress((void**)&scr1, g_scr1);

    const size_t MM = (size_t)DN * DN;

    k_pass1<<<BATCH * CH, 256>>>(in, outAll);
    // Hillis-Steele over chunk totals: totals live at element (c+1)*CL-1 of outAll
    k_scan<<<BATCH * CH, 256>>>(outAll, (size_t)(CL - 1) * MM,
                                (size_t)SEQ * MM, (size_t)CL * MM, scr0, 1);
    k_scan<<<BATCH * CH, 256>>>(scr0, 0, (size_t)CH * MM, MM, scr1, 2);
    k_scan<<<BATCH * CH, 256>>>(scr1, 0, (size_t)CH * MM, MM, scr0, 4);
    k_scan<<<BATCH * CH, 256>>>(scr0, 0, (size_t)CH * MM, MM, scr1, 8);
    k_pass3<<<BATCH * (CH - 1) * CL, 256>>>(outAll, scr1);
    k_copy_x<<<BATCH, 256>>>(outAll, x);
}

// round 7
// speedup vs baseline: 2.1894x; 2.1844x over previous
#include <cuda_runtime.h>
#include <cstdint>

// Cumulative matrix product (associative scan of matmul) over axis 1.
// input:  (32, 256, 128, 128) fp32
// output: x (32,128,128) followed by all_outputs (32,256,128,128), flat.
//
// Chunked scan (4 passes). Matmul core: fp16 m16n8k16 tensor MMA with 3-term
// split (hh + lh + hl; fp16 significand == tf32 significand), ldmatrix
// fragment loads, packed f16x2 splits, register prefetch of the next k-slab.

#define DN 128
#define BATCH 32
#define SEQ 256
#define CH 16
#define CL 16

#define ASTRU 12   // A smem row stride in uint (24 halves = 48B -> conflict-free ldmatrix)
#define BSTRU 68   // B smem row stride in uint (136 halves = 272B -> conflict-free ldmatrix)

__device__ float g_scr0[(size_t)BATCH * CH * DN * DN];
__device__ float g_scr1[(size_t)BATCH * CH * DN * DN];

__device__ __forceinline__ unsigned smem_u32(const void* p) {
    unsigned a;
    asm("{ .reg .u64 t; cvta.to.shared.u64 t, %1; cvt.u32.u64 %0, t; }" : "=r"(a) : "l"(p));
    return a;
}

// pack two f32 -> half2 {lo, hi}
__device__ __forceinline__ unsigned pack2h(float lo, float hi) {
    unsigned r;
    asm("cvt.rn.f16x2.f32 %0, %1, %2;" : "=r"(r) : "f"(hi), "f"(lo));
    return r;
}
__device__ __forceinline__ float2 h2f(unsigned h) {
    float2 f;
    asm("{ .reg .f16 a, b;\n\t mov.b32 {a, b}, %2;\n\t"
        " cvt.f32.f16 %0, a;\n\t cvt.f32.f16 %1, b; }"
        : "=f"(f.x), "=f"(f.y) : "r"(h));
    return f;
}
// split 4 floats into hi-half2 pair and lo-half2 pair
__device__ __forceinline__ void split4(float4 v, unsigned& h0, unsigned& h1,
                                       unsigned& l0, unsigned& l1) {
    h0 = pack2h(v.x, v.y);
    h1 = pack2h(v.z, v.w);
    float2 f0 = h2f(h0), f1 = h2f(h1);
    l0 = pack2h(v.x - f0.x, v.y - f0.y);
    l1 = pack2h(v.z - f1.x, v.w - f1.y);
}

__device__ __forceinline__ void ldsm4(unsigned r[4], unsigned addr) {
    asm volatile("ldmatrix.sync.aligned.m8n8.x4.shared.b16 {%0,%1,%2,%3}, [%4];"
                 : "=r"(r[0]), "=r"(r[1]), "=r"(r[2]), "=r"(r[3]) : "r"(addr));
}
__device__ __forceinline__ void ldsm4t(unsigned r[4], unsigned addr) {
    asm volatile("ldmatrix.sync.aligned.m8n8.x4.trans.shared.b16 {%0,%1,%2,%3}, [%4];"
                 : "=r"(r[0]), "=r"(r[1]), "=r"(r[2]), "=r"(r[3]) : "r"(addr));
}
__device__ __forceinline__ void mma16(float c[4], const unsigned a[4],
                                      unsigned b0, unsigned b1) {
    asm volatile(
        "mma.sync.aligned.m16n8k16.row.col.f32.f16.f16.f32 "
        "{%0,%1,%2,%3},{%4,%5,%6,%7},{%8,%9},{%0,%1,%2,%3};"
        : "+f"(c[0]), "+f"(c[1]), "+f"(c[2]), "+f"(c[3])
        : "r"(a[0]), "r"(a[1]), "r"(a[2]), "r"(a[3]), "r"(b0), "r"(b1));
}

__device__ __forceinline__ void copy128(const float* __restrict__ s, float* __restrict__ d) {
    const float4* s4 = (const float4*)s;
    float4* d4 = (float4*)d;
#pragma unroll
    for (int i = threadIdx.x; i < DN * DN / 4; i += 256) d4[i] = s4[i];
}

// 256 threads (8 warps, 64x32 warp tiles): C = A @ B, 128x128 row-major fp32.
// 3-term fp16 decomposition, fp32 accumulate. C may alias B: every global B
// read (prefetch) precedes the final pre-MMA __syncthreads of the last slab;
// C stores happen after all MMAs. Chained calls (C of call j-1 = A of call j)
// are safe via the entry __syncthreads.
__device__ __forceinline__ void mm128(const float* __restrict__ A,
                                      const float* __restrict__ B,
                                      float* __restrict__ C) {
    __shared__ __align__(16) unsigned Ah[DN * ASTRU], Al[DN * ASTRU];
    __shared__ __align__(16) unsigned Bh[16 * BSTRU], Bl[16 * BSTRU];

    const int tid = threadIdx.x;
    const int lane = tid & 31, w = tid >> 5;
    const int wm = (w >> 2) * 64, wn = (w & 3) * 32;

    // split-phase mapping
    const int am = tid >> 1, aku = tid & 1;         // A: row, k-half(8)
    const int bk = tid >> 4, bn = (tid & 15) * 8;   // B: k-row, n0

    const unsigned aBaseH = smem_u32(Ah), aBaseL = smem_u32(Al);
    const unsigned bBaseH = smem_u32(Bh), bBaseL = smem_u32(Bl);
    // ldmatrix per-lane offsets: A tiles (m0k0, m8k0, m0k8, m8k8); B tiles
    // (k0n0, k8n0, k0n8, k8n8) with .trans
    const unsigned aoff = (unsigned)(((lane & 7) + (lane & 8)) * 48 + (lane >> 4) * 16);
    const unsigned boff = (unsigned)(((lane & 7) + (lane & 8)) * 272 + (lane >> 4) * 16);

    float acc[4][4][4];
#pragma unroll
    for (int mt = 0; mt < 4; mt++)
#pragma unroll
        for (int nt = 0; nt < 4; nt++)
#pragma unroll
            for (int i = 0; i < 4; i++) acc[mt][nt][i] = 0.0f;

    __syncthreads();  // prior epilogue/copy stores visible before reading A/B

    float4 va0 = *(const float4*)&A[(size_t)am * DN + aku * 8];
    float4 va1 = *(const float4*)&A[(size_t)am * DN + aku * 8 + 4];
    float4 vb0 = *(const float4*)&B[(size_t)bk * DN + bn];
    float4 vb1 = *(const float4*)&B[(size_t)bk * DN + bn + 4];

    for (int s = 0; s < 8; s++) {
        // split + store slab s (regs already hold it)
        {
            unsigned h0, h1, l0, l1, h2, h3, l2, l3;
            split4(va0, h0, h1, l0, l1);
            split4(va1, h2, h3, l2, l3);
            *(uint4*)&Ah[am * ASTRU + aku * 4] = make_uint4(h0, h1, h2, h3);
            *(uint4*)&Al[am * ASTRU + aku * 4] = make_uint4(l0, l1, l2, l3);
            split4(vb0, h0, h1, l0, l1);
            split4(vb1, h2, h3, l2, l3);
            *(uint4*)&Bh[bk * BSTRU + (bn >> 1)] = make_uint4(h0, h1, h2, h3);
            *(uint4*)&Bl[bk * BSTRU + (bn >> 1)] = make_uint4(l0, l1, l2, l3);
        }
        __syncthreads();

        // prefetch slab s+1 while MMAs run
        if (s < 7) {
            const int k0 = (s + 1) * 16;
            va0 = *(const float4*)&A[(size_t)am * DN + k0 + aku * 8];
            va1 = *(const float4*)&A[(size_t)am * DN + k0 + aku * 8 + 4];
            vb0 = *(const float4*)&B[(size_t)(k0 + bk) * DN + bn];
            vb1 = *(const float4*)&B[(size_t)(k0 + bk) * DN + bn + 4];
        }

        // 3 terms: Ah*Bh, Al*Bh, Ah*Bl (term-major keeps frag regs small)
#pragma unroll
        for (int t = 0; t < 3; t++) {
            const unsigned aB = (t == 1) ? aBaseL : aBaseH;
            const unsigned bB = (t == 2) ? bBaseL : bBaseH;
            unsigned af[4][4];
#pragma unroll
            for (int mt = 0; mt < 4; mt++)
                ldsm4(af[mt], aB + (unsigned)((wm + mt * 16) * 48) + aoff);
            unsigned bf[2][4];
#pragma unroll
            for (int np = 0; np < 2; np++)
                ldsm4t(bf[np], bB + (unsigned)((wn + np * 16) * 2) + boff);
#pragma unroll
            for (int mt = 0; mt < 4; mt++)
#pragma unroll
                for (int nt = 0; nt < 4; nt++)
                    mma16(acc[mt][nt], af[mt], bf[nt >> 1][(nt & 1) * 2],
                          bf[nt >> 1][(nt & 1) * 2 + 1]);
        }
        __syncthreads();
    }

    // epilogue: all global B reads retired block-wide (alias-safe)
#pragma unroll
    for (int mt = 0; mt < 4; mt++)
#pragma unroll
        for (int nt = 0; nt < 4; nt++) {
            const int r0 = wm + mt * 16 + (lane >> 2);
            const int c0 = wn + nt * 8 + (lane & 3) * 2;
            *(float2*)&C[(size_t)r0 * DN + c0] = make_float2(acc[mt][nt][0], acc[mt][nt][1]);
            *(float2*)&C[(size_t)(r0 + 8) * DN + c0] = make_float2(acc[mt][nt][2], acc[mt][nt][3]);
        }
}

// Pass 1: local prefix products within each chunk.
__global__ void __launch_bounds__(256, 2) k_pass1(const float* __restrict__ in,
                                                  float* __restrict__ outAll) {
    const int b = blockIdx.x / CH, c = blockIdx.x % CH;
    const size_t base = ((size_t)b * SEQ + (size_t)c * CL) * (DN * DN);
    const float* E = in + base;
    float* O = outAll + base;
    copy128(E, O);
    for (int j = 1; j < CL; j++)
        mm128(O + (size_t)(j - 1) * DN * DN, E + (size_t)j * DN * DN,
              O + (size_t)j * DN * DN);
}

// Pass 2 step (Hillis-Steele over chunk totals).
__global__ void __launch_bounds__(256, 2) k_scan(const float* __restrict__ src,
                                                 size_t soff, size_t sb, size_t si,
                                                 float* __restrict__ dst, int d) {
    const int b = blockIdx.x / CH, i = blockIdx.x % CH;
    const float* Ti = src + soff + (size_t)b * sb + (size_t)i * si;
    float* Dp = dst + ((size_t)b * CH + i) * (DN * DN);
    if (i < d) { copy128(Ti, Dp); return; }
    mm128(src + soff + (size_t)b * sb + (size_t)(i - d) * si, Ti, Dp);
}

// Pass 3: apply exclusive chunk prefix to chunks 1..CH-1 (in place).
__global__ void __launch_bounds__(256, 2) k_pass3(float* __restrict__ outAll,
                                                  const float* __restrict__ scan) {
    int idx = blockIdx.x;
    const int j = idx % CL; idx /= CL;
    const int c = (idx % (CH - 1)) + 1; idx /= (CH - 1);
    const int b = idx;
    const float* A = scan + ((size_t)b * CH + (c - 1)) * (DN * DN);
    float* Bp = outAll + ((size_t)b * SEQ + (size_t)c * CL + j) * (DN * DN);
    mm128(A, Bp, Bp);
}

// Pass 4: x[b] = all_outputs[b, SEQ-1]
__global__ void __launch_bounds__(256) k_copy_x(const float* __restrict__ outAll,
                                                float* __restrict__ x) {
    copy128(outAll + ((size_t)blockIdx.x * SEQ + (SEQ - 1)) * (DN * DN),
            x + (size_t)blockIdx.x * DN * DN);
}

extern "C" void kernel_launch(void* const* d_in, const int* in_sizes, int n_in,
                              void* d_out, int out_size) {
    const float* in = (const float*)d_in[0];
    float* out = (float*)d_out;
    float* x = out;                                  // first 32*128*128 elements
    float* outAll = out + (size_t)BATCH * DN * DN;   // then 32*256*128*128

    float *scr0, *scr1;
    cudaGetSymbolAddress((void**)&scr0, g_scr0);
    cudaGetSymbolAddress((void**)&scr1, g_scr1);

    const size_t MM = (size_t)DN * DN;

    k_pass1<<<BATCH * CH, 256>>>(in, outAll);
    k_scan<<<BATCH * CH, 256>>>(outAll, (size_t)(CL - 1) * MM,
                                (size_t)SEQ * MM, (size_t)CL * MM, scr0, 1);
    k_scan<<<BATCH * CH, 256>>>(scr0, 0, (size_t)CH * MM, MM, scr1, 2);
    k_scan<<<BATCH * CH, 256>>>(scr1, 0, (size_t)CH * MM, MM, scr0, 4);
    k_scan<<<BATCH * CH, 256>>>(scr0, 0, (size_t)CH * MM, MM, scr1, 8);
    k_pass3<<<BATCH * (CH - 1) * CL, 256>>>(outAll, scr1);
    k_copy_x<<<BATCH, 256>>>(outAll, x);
}